// round 1
// baseline (speedup 1.0000x reference)
#include <cuda_runtime.h>
#include <math.h>

#define NHEADS 16
#define HDIM   128
#define DIM    2048
#define WIN    512
#define SEQ_MAX 4096

// ---------------- scratch (static device globals: allowed) ----------------
__device__ float g_q[(size_t)NHEADS * SEQ_MAX * HDIM];
__device__ float g_k[(size_t)NHEADS * SEQ_MAX * HDIM];
__device__ float g_v[(size_t)NHEADS * SEQ_MAX * HDIM];
__device__ float g_attn[(size_t)SEQ_MAX * DIM];

// ---------------- f32x2 packed math helpers ----------------
__device__ __forceinline__ unsigned long long pack2(float x, float y) {
    unsigned long long r;
    asm("mov.b64 %0, {%1,%2};" : "=l"(r) : "f"(x), "f"(y));
    return r;
}
__device__ __forceinline__ void unpack2(unsigned long long v, float& x, float& y) {
    asm("mov.b64 {%0,%1}, %2;" : "=f"(x), "=f"(y) : "l"(v));
}
__device__ __forceinline__ unsigned long long fma2(unsigned long long a,
                                                   unsigned long long b,
                                                   unsigned long long c) {
    unsigned long long d;
    asm("fma.rn.f32x2 %0, %1, %2, %3;" : "=l"(d) : "l"(a), "l"(b), "l"(c));
    return d;
}

// ---------------- GEMM: C = A[M,K] @ B[N,K]^T  (TN, both K-major) ----------
// MODE 0: plain row-major C[m*DIM + n]            (output projection)
// MODE 1: RoPE + head-major C[head][m][d]          (Q, K)
// MODE 2: head-major C[head][m][d], no RoPE        (V)
template <int MODE>
__global__ void __launch_bounds__(256, 2)
gemm_tn(const float* __restrict__ A, const float* __restrict__ B,
        float* __restrict__ C, int M) {
    const int K = DIM;
    const int N = DIM;
    __shared__ float As[16 * 132];   // As[k][m], padded
    __shared__ float Bs[16 * 132];   // Bs[k][n], padded

    int tid = threadIdx.x;
    int bn = blockIdx.x * 128;
    int bm = blockIdx.y * 128;
    int tx = tid & 15;
    int ty = tid >> 4;
    int m0 = ty * 8;
    int n0 = tx * 8;

    unsigned long long acc[8][4];
#pragma unroll
    for (int i = 0; i < 8; i++)
#pragma unroll
        for (int j = 0; j < 4; j++) acc[i][j] = 0ull;

    for (int k0 = 0; k0 < K; k0 += 16) {
#pragma unroll
        for (int it = 0; it < 2; it++) {
            int f = tid + it * 256;        // 0..511
            int row = f >> 2;              // 0..127
            int kq = (f & 3) << 2;         // 0,4,8,12
            float4 av = *(const float4*)&A[(size_t)(bm + row) * K + k0 + kq];
            As[(kq + 0) * 132 + row] = av.x;
            As[(kq + 1) * 132 + row] = av.y;
            As[(kq + 2) * 132 + row] = av.z;
            As[(kq + 3) * 132 + row] = av.w;
            float4 bv = *(const float4*)&B[(size_t)(bn + row) * K + k0 + kq];
            Bs[(kq + 0) * 132 + row] = bv.x;
            Bs[(kq + 1) * 132 + row] = bv.y;
            Bs[(kq + 2) * 132 + row] = bv.z;
            Bs[(kq + 3) * 132 + row] = bv.w;
        }
        __syncthreads();
#pragma unroll
        for (int k = 0; k < 16; k++) {
            unsigned long long b2[4];
#pragma unroll
            for (int jp = 0; jp < 4; jp++)
                b2[jp] = *(const unsigned long long*)&Bs[k * 132 + n0 + 2 * jp];
#pragma unroll
            for (int i = 0; i < 8; i++) {
                float av = As[k * 132 + m0 + i];
                unsigned long long a2 = pack2(av, av);
#pragma unroll
                for (int jp = 0; jp < 4; jp++)
                    acc[i][jp] = fma2(a2, b2[jp], acc[i][jp]);
            }
        }
        __syncthreads();
    }

    // ---- epilogue ----
#pragma unroll
    for (int i = 0; i < 8; i++) {
        int m = bm + m0 + i;
#pragma unroll
        for (int jp = 0; jp < 4; jp++) {
            float x1, x2;
            unpack2(acc[i][jp], x1, x2);
            int n = bn + n0 + 2 * jp;
            if (MODE == 0) {
                C[(size_t)m * N + n]     = x1;
                C[(size_t)m * N + n + 1] = x2;
            } else {
                int head = n >> 7;
                int d = n & 127;
                float o1 = x1, o2 = x2;
                if (MODE == 1) {
                    // inv_freq = 10000^(-d/128), d even; double for accuracy,
                    // then fp32 angle multiply to match the jax fp32 reference.
                    float expo = (float)d * (1.0f / 128.0f);
                    float inv_freq = (float)exp(-(double)expo * 9.210340371976184);
                    float ang = (float)m * inv_freq;
                    float sn, cs;
                    sincosf(ang, &sn, &cs);
                    o1 = x1 * cs - x2 * sn;
                    o2 = x1 * sn + x2 * cs;
                }
                size_t idx = ((size_t)head * M + m) * HDIM + d;
                C[idx]     = o1;
                C[idx + 1] = o2;
            }
        }
    }
}

// ---------------- windowed flash attention ----------------
// Q/K/V layout: [head][seq][128]. Output: [seq][head*128+d] (row-major [seq, DIM]).
#define BQ 64
#define BK 64
#define RPAD 129
#define SPAD 65

__global__ void __launch_bounds__(256, 1)
attn_kernel(const float* __restrict__ Q, const float* __restrict__ K,
            const float* __restrict__ V, float* __restrict__ O, int seq) {
    extern __shared__ float sm[];
    float* Qs  = sm;                       // 64 x 129
    float* Ks  = Qs + BQ * RPAD;           // 64 x 129
    float* Vs  = Ks + BK * RPAD;           // 64 x 129
    float* Ssc = Vs + BK * RPAD;           // 64 x 65
    float* rm  = Ssc + BQ * SPAD;          // 64
    float* rl  = rm + BQ;                  // 64
    float* ral = rl + BQ;                  // 64

    int t = threadIdx.x;
    int head = blockIdx.y;
    int q0 = blockIdx.x * BQ;

    const float* Qh = Q + ((size_t)head * seq + q0) * HDIM;
    const float* Kh = K + (size_t)head * seq * HDIM;
    const float* Vh = V + (size_t)head * seq * HDIM;

    // load Q block
    for (int f = t; f < BQ * HDIM / 4; f += 256) {
        float4 v = ((const float4*)Qh)[f];
        int row = f >> 5;
        int c4 = (f & 31) << 2;
        float* d = &Qs[row * RPAD + c4];
        d[0] = v.x; d[1] = v.y; d[2] = v.z; d[3] = v.w;
    }
    if (t < BQ) { rm[t] = -INFINITY; rl[t] = 0.f; }

    float acc[32];
#pragma unroll
    for (int j = 0; j < 32; j++) acc[j] = 0.f;
    int r_pv = t >> 2;        // 0..63
    int cph  = t & 3;         // column phase (stride-4 interleave)

    int r0 = (t >> 4) << 2;   // 4 rows for S compute
    int c0 = (t & 15) << 2;   // 4 cols for S compute

    const float scale = 0.08838834764831845f;  // 128^-0.5
    int kb_start = (q0 >= (WIN - 1)) ? ((q0 - (WIN - 1)) >> 6) : 0;
    int kb_end = q0 >> 6;

    for (int kb = kb_start; kb <= kb_end; ++kb) {
        int k0 = kb << 6;
        __syncthreads();  // previous PV done before overwriting Ks/Vs/Ssc
        for (int f = t; f < BK * HDIM / 4; f += 256) {
            int row = f >> 5;
            int c4 = (f & 31) << 2;
            float4 kv = ((const float4*)(Kh + (size_t)k0 * HDIM))[f];
            float* dk = &Ks[row * RPAD + c4];
            dk[0] = kv.x; dk[1] = kv.y; dk[2] = kv.z; dk[3] = kv.w;
            float4 vv = ((const float4*)(Vh + (size_t)k0 * HDIM))[f];
            float* dv = &Vs[row * RPAD + c4];
            dv[0] = vv.x; dv[1] = vv.y; dv[2] = vv.z; dv[3] = vv.w;
        }
        __syncthreads();

        // S = (Q K^T) * scale with window/causal mask
        float sacc[4][4];
#pragma unroll
        for (int i = 0; i < 4; i++)
#pragma unroll
            for (int j = 0; j < 4; j++) sacc[i][j] = 0.f;

#pragma unroll 4
        for (int k = 0; k < HDIM; k++) {
            float a_[4], b_[4];
#pragma unroll
            for (int i = 0; i < 4; i++) a_[i] = Qs[(r0 + i) * RPAD + k];
#pragma unroll
            for (int j = 0; j < 4; j++) b_[j] = Ks[(c0 + j) * RPAD + k];
#pragma unroll
            for (int i = 0; i < 4; i++)
#pragma unroll
                for (int j = 0; j < 4; j++) sacc[i][j] += a_[i] * b_[j];
        }
#pragma unroll
        for (int i = 0; i < 4; i++) {
            int qr = q0 + r0 + i;
#pragma unroll
            for (int j = 0; j < 4; j++) {
                int kc = k0 + c0 + j;
                bool valid = (kc <= qr) && (qr - kc < WIN);
                Ssc[(r0 + i) * SPAD + (c0 + j)] =
                    valid ? sacc[i][j] * scale : -INFINITY;
            }
        }
        __syncthreads();

        // online softmax, one thread per row
        if (t < BQ) {
            int r = t;
            float mold = rm[r];
            float mb = -INFINITY;
#pragma unroll 8
            for (int c = 0; c < BK; c++) mb = fmaxf(mb, Ssc[r * SPAD + c]);
            float mnew = fmaxf(mold, mb);
            float a, ls = 0.f;
            if (mnew == -INFINITY) {  // nothing valid yet in this row
                a = 1.f;
#pragma unroll 8
                for (int c = 0; c < BK; c++) Ssc[r * SPAD + c] = 0.f;
            } else {
                a = expf(mold - mnew);  // mold=-inf -> 0
#pragma unroll 8
                for (int c = 0; c < BK; c++) {
                    float p = expf(Ssc[r * SPAD + c] - mnew);
                    Ssc[r * SPAD + c] = p;
                    ls += p;
                }
            }
            rl[r] = rl[r] * a + ls;
            rm[r] = mnew;
            ral[r] = a;
        }
        __syncthreads();

        // O += P @ V  (rescale old acc by alpha first)
        float a = ral[r_pv];
#pragma unroll
        for (int j = 0; j < 32; j++) acc[j] *= a;
        for (int c = 0; c < BK; c++) {
            float p = Ssc[r_pv * SPAD + c];
            const float* vrow = &Vs[c * RPAD + cph];
#pragma unroll
            for (int j = 0; j < 32; j++) acc[j] += p * vrow[j * 4];
        }
    }

    // normalize + store to [seq, DIM] layout
    float inv = 1.0f / rl[r_pv];
    float* Orow = O + (size_t)(q0 + r_pv) * DIM + head * HDIM + cph;
#pragma unroll
    for (int j = 0; j < 32; j++) Orow[j * 4] = acc[j] * inv;
}

// ---------------- launch ----------------
extern "C" void kernel_launch(void* const* d_in, const int* in_sizes, int n_in,
                              void* d_out, int out_size) {
    const float* x  = (const float*)d_in[0];
    const float* Wq = (const float*)d_in[1];
    const float* Wk = (const float*)d_in[2];
    const float* Wv = (const float*)d_in[3];
    const float* Wo = (const float*)d_in[4];
    float* out = (float*)d_out;

    int seq = in_sizes[0] / DIM;  // 4096

    float* q = nullptr; float* k = nullptr; float* v = nullptr; float* attn = nullptr;
    cudaGetSymbolAddress((void**)&q, g_q);
    cudaGetSymbolAddress((void**)&k, g_k);
    cudaGetSymbolAddress((void**)&v, g_v);
    cudaGetSymbolAddress((void**)&attn, g_attn);

    dim3 gg(DIM / 128, seq / 128);
    gemm_tn<1><<<gg, 256>>>(x, Wq, q, seq);
    gemm_tn<1><<<gg, 256>>>(x, Wk, k, seq);
    gemm_tn<2><<<gg, 256>>>(x, Wv, v, seq);

    const int smem_attn = (3 * BQ * RPAD + BQ * SPAD + 3 * BQ) * sizeof(float);
    cudaFuncSetAttribute(attn_kernel, cudaFuncAttributeMaxDynamicSharedMemorySize,
                         smem_attn);
    attn_kernel<<<dim3(seq / BQ, NHEADS), 256, smem_attn>>>(q, k, v, attn, seq);

    gemm_tn<0><<<gg, 256>>>(attn, Wo, out, seq);
}

// round 7
// speedup vs baseline: 1.9457x; 1.9457x over previous
#include <cuda_runtime.h>
#include <math.h>
#include <stdint.h>

#define NHEADS 16
#define HDIM   128
#define DIM    2048
#define WIN    512
#define SEQ_MAX 4096
#define S20    20   // smem row stride (floats): conflict-free + 16B aligned

// ---------------- scratch ----------------
__device__ float g_q[(size_t)NHEADS * SEQ_MAX * HDIM];
__device__ float g_k[(size_t)NHEADS * SEQ_MAX * HDIM];
__device__ float g_v[(size_t)NHEADS * SEQ_MAX * HDIM];
__device__ float g_attn[(size_t)SEQ_MAX * DIM];

// ---------------- helpers ----------------
__device__ __forceinline__ float tf32r(float x) {
    float y;
    asm("cvt.rna.tf32.f32 %0, %1;" : "=f"(y) : "f"(x));
    return y;
}
__device__ __forceinline__ void st4tf(float* p, float4 v) {
    float4 w = make_float4(tf32r(v.x), tf32r(v.y), tf32r(v.z), tf32r(v.w));
    *(float4*)p = w;
}
__device__ __forceinline__ void mma8(float* d, const uint32_t* a, const uint32_t* b) {
    asm volatile(
        "mma.sync.aligned.m16n8k8.row.col.f32.tf32.tf32.f32 "
        "{%0,%1,%2,%3}, {%4,%5,%6,%7}, {%8,%9}, {%0,%1,%2,%3};"
        : "+f"(d[0]), "+f"(d[1]), "+f"(d[2]), "+f"(d[3])
        : "r"(a[0]), "r"(a[1]), "r"(a[2]), "r"(a[3]), "r"(b[0]), "r"(b[1]));
}

// ---------------- tf32 mma.sync GEMM: C = A[M,2048] @ B[2048,2048]^T ------
// Tile 128x128, 8 warps (2 n x 4 m), warp tile 32(m) x 64(n).
// MODE 0: row-major C.  MODE 1: RoPE + head-major.  MODE 2: head-major.
template <int MODE>
__global__ void __launch_bounds__(256, 2)
gemm_mma(const float* __restrict__ A, const float* __restrict__ B,
         float* __restrict__ C, int M) {
    __shared__ float As[2][128 * S20];
    __shared__ float Bs[2][128 * S20];

    const int tid = threadIdx.x, wid = tid >> 5, lane = tid & 31;
    const int g = lane >> 2, tg = lane & 3;
    const int bm = blockIdx.y * 128, bn = blockIdx.x * 128;
    const int wm = (wid >> 1) * 32, wn = (wid & 1) * 64;

    float c[2][8][4];
#pragma unroll
    for (int mt = 0; mt < 2; mt++)
#pragma unroll
        for (int nt = 0; nt < 8; nt++)
#pragma unroll
            for (int j = 0; j < 4; j++) c[mt][nt][j] = 0.f;

    const int lr = tid >> 2;           // 0..63
    const int lk = (tid & 3) << 2;     // 0,4,8,12
    const float* Ap = A + (size_t)(bm + lr) * DIM + lk;
    const float* Bp = B + (size_t)(bn + lr) * DIM + lk;

    // preload chunk 0
    {
        float4 a0 = *(const float4*)Ap;
        float4 a1 = *(const float4*)(Ap + (size_t)64 * DIM);
        float4 b0 = *(const float4*)Bp;
        float4 b1 = *(const float4*)(Bp + (size_t)64 * DIM);
        st4tf(&As[0][lr * S20 + lk], a0);
        st4tf(&As[0][(lr + 64) * S20 + lk], a1);
        st4tf(&Bs[0][lr * S20 + lk], b0);
        st4tf(&Bs[0][(lr + 64) * S20 + lk], b1);
    }
    __syncthreads();

    for (int kc = 0; kc < DIM / 16; kc++) {
        const int cur = kc & 1;
        float4 a0, a1, b0, b1;
        if (kc < DIM / 16 - 1) {
            const float* ap = Ap + (kc + 1) * 16;
            const float* bp = Bp + (kc + 1) * 16;
            a0 = *(const float4*)ap;
            a1 = *(const float4*)(ap + (size_t)64 * DIM);
            b0 = *(const float4*)bp;
            b1 = *(const float4*)(bp + (size_t)64 * DIM);
        }
#pragma unroll
        for (int s = 0; s < 2; s++) {
            uint32_t af[2][4], bf[8][2];
#pragma unroll
            for (int mt = 0; mt < 2; mt++) {
                const float* base = &As[cur][(wm + mt * 16) * S20 + s * 8];
                af[mt][0] = __float_as_uint(base[g * S20 + tg]);
                af[mt][1] = __float_as_uint(base[(g + 8) * S20 + tg]);
                af[mt][2] = __float_as_uint(base[g * S20 + tg + 4]);
                af[mt][3] = __float_as_uint(base[(g + 8) * S20 + tg + 4]);
            }
#pragma unroll
            for (int nt = 0; nt < 8; nt++) {
                const float* base = &Bs[cur][(wn + nt * 8 + g) * S20 + s * 8];
                bf[nt][0] = __float_as_uint(base[tg]);
                bf[nt][1] = __float_as_uint(base[tg + 4]);
            }
#pragma unroll
            for (int mt = 0; mt < 2; mt++)
#pragma unroll
                for (int nt = 0; nt < 8; nt++)
                    mma8(c[mt][nt], af[mt], bf[nt]);
        }
        if (kc < DIM / 16 - 1) {
            const int nxt = cur ^ 1;
            st4tf(&As[nxt][lr * S20 + lk], a0);
            st4tf(&As[nxt][(lr + 64) * S20 + lk], a1);
            st4tf(&Bs[nxt][lr * S20 + lk], b0);
            st4tf(&Bs[nxt][(lr + 64) * S20 + lk], b1);
            __syncthreads();
        }
    }

    // ---- epilogue (fragment layout: rows g, g+8; cols 2*tg, 2*tg+1) ----
#pragma unroll
    for (int mt = 0; mt < 2; mt++) {
#pragma unroll
        for (int nt = 0; nt < 8; nt++) {
            const int n = bn + wn + nt * 8 + 2 * tg;
#pragma unroll
            for (int half = 0; half < 2; half++) {
                const int m = bm + wm + mt * 16 + g + half * 8;
                float x1 = c[mt][nt][half * 2];
                float x2 = c[mt][nt][half * 2 + 1];
                if (MODE == 0) {
                    *(float2*)&C[(size_t)m * DIM + n] = make_float2(x1, x2);
                } else {
                    const int head = n >> 7, d = n & 127;
                    float o1 = x1, o2 = x2;
                    if (MODE == 1) {
                        float expo = (float)d * (1.0f / 128.0f);
                        float inv_freq = (float)exp(-(double)expo * 9.210340371976184);
                        float ang = (float)m * inv_freq;
                        float sn, cs;
                        sincosf(ang, &sn, &cs);
                        o1 = x1 * cs - x2 * sn;
                        o2 = x1 * sn + x2 * cs;
                    }
                    size_t idx = ((size_t)head * M + m) * HDIM + d;
                    *(float2*)&C[idx] = make_float2(o1, o2);
                }
            }
        }
    }
}

// ---------------- windowed flash attention (round-1, proven) ----------------
#define BQ 64
#define BK 64
#define RPAD 129
#define SPAD 65

__global__ void __launch_bounds__(256, 1)
attn_kernel(const float* __restrict__ Q, const float* __restrict__ K,
            const float* __restrict__ V, float* __restrict__ O, int seq) {
    extern __shared__ float smf[];
    float* Qs  = smf;
    float* Ks  = Qs + BQ * RPAD;
    float* Vs  = Ks + BK * RPAD;
    float* Ssc = Vs + BK * RPAD;
    float* rm  = Ssc + BQ * SPAD;
    float* rl  = rm + BQ;
    float* ral = rl + BQ;

    int t = threadIdx.x;
    int head = blockIdx.y;
    int q0 = blockIdx.x * BQ;

    const float* Qh = Q + ((size_t)head * seq + q0) * HDIM;
    const float* Kh = K + (size_t)head * seq * HDIM;
    const float* Vh = V + (size_t)head * seq * HDIM;

    for (int f = t; f < BQ * HDIM / 4; f += 256) {
        float4 v = ((const float4*)Qh)[f];
        int row = f >> 5;
        int c4 = (f & 31) << 2;
        float* d = &Qs[row * RPAD + c4];
        d[0] = v.x; d[1] = v.y; d[2] = v.z; d[3] = v.w;
    }
    if (t < BQ) { rm[t] = -INFINITY; rl[t] = 0.f; }

    float acc[32];
#pragma unroll
    for (int j = 0; j < 32; j++) acc[j] = 0.f;
    int r_pv = t >> 2;
    int cph  = t & 3;

    int r0 = (t >> 4) << 2;
    int c0 = (t & 15) << 2;

    const float scale = 0.08838834764831845f;
    int kb_start = (q0 >= (WIN - 1)) ? ((q0 - (WIN - 1)) >> 6) : 0;
    int kb_end = q0 >> 6;

    for (int kb = kb_start; kb <= kb_end; ++kb) {
        int k0 = kb << 6;
        __syncthreads();
        for (int f = t; f < BK * HDIM / 4; f += 256) {
            int row = f >> 5;
            int c4 = (f & 31) << 2;
            float4 kv = ((const float4*)(Kh + (size_t)k0 * HDIM))[f];
            float* dk = &Ks[row * RPAD + c4];
            dk[0] = kv.x; dk[1] = kv.y; dk[2] = kv.z; dk[3] = kv.w;
            float4 vv = ((const float4*)(Vh + (size_t)k0 * HDIM))[f];
            float* dv = &Vs[row * RPAD + c4];
            dv[0] = vv.x; dv[1] = vv.y; dv[2] = vv.z; dv[3] = vv.w;
        }
        __syncthreads();

        float sacc[4][4];
#pragma unroll
        for (int i = 0; i < 4; i++)
#pragma unroll
            for (int j = 0; j < 4; j++) sacc[i][j] = 0.f;

#pragma unroll 4
        for (int k = 0; k < HDIM; k++) {
            float a_[4], b_[4];
#pragma unroll
            for (int i = 0; i < 4; i++) a_[i] = Qs[(r0 + i) * RPAD + k];
#pragma unroll
            for (int j = 0; j < 4; j++) b_[j] = Ks[(c0 + j) * RPAD + k];
#pragma unroll
            for (int i = 0; i < 4; i++)
#pragma unroll
                for (int j = 0; j < 4; j++) sacc[i][j] += a_[i] * b_[j];
        }
#pragma unroll
        for (int i = 0; i < 4; i++) {
            int qr = q0 + r0 + i;
#pragma unroll
            for (int j = 0; j < 4; j++) {
                int kc = k0 + c0 + j;
                bool valid = (kc <= qr) && (qr - kc < WIN);
                Ssc[(r0 + i) * SPAD + (c0 + j)] =
                    valid ? sacc[i][j] * scale : -INFINITY;
            }
        }
        __syncthreads();

        if (t < BQ) {
            int r = t;
            float mold = rm[r];
            float mb = -INFINITY;
#pragma unroll 8
            for (int c = 0; c < BK; c++) mb = fmaxf(mb, Ssc[r * SPAD + c]);
            float mnew = fmaxf(mold, mb);
            float a, ls = 0.f;
            if (mnew == -INFINITY) {
                a = 1.f;
#pragma unroll 8
                for (int c = 0; c < BK; c++) Ssc[r * SPAD + c] = 0.f;
            } else {
                a = expf(mold - mnew);
#pragma unroll 8
                for (int c = 0; c < BK; c++) {
                    float p = expf(Ssc[r * SPAD + c] - mnew);
                    Ssc[r * SPAD + c] = p;
                    ls += p;
                }
            }
            rl[r] = rl[r] * a + ls;
            rm[r] = mnew;
            ral[r] = a;
        }
        __syncthreads();

        float a = ral[r_pv];
#pragma unroll
        for (int j = 0; j < 32; j++) acc[j] *= a;
        for (int c = 0; c < BK; c++) {
            float p = Ssc[r_pv * SPAD + c];
            const float* vrow = &Vs[c * RPAD + cph];
#pragma unroll
            for (int j = 0; j < 32; j++) acc[j] += p * vrow[j * 4];
        }
    }

    float inv = 1.0f / rl[r_pv];
    float* Orow = O + (size_t)(q0 + r_pv) * DIM + head * HDIM + cph;
#pragma unroll
    for (int j = 0; j < 32; j++) Orow[j * 4] = acc[j] * inv;
}

// ---------------- launch ----------------
extern "C" void kernel_launch(void* const* d_in, const int* in_sizes, int n_in,
                              void* d_out, int out_size) {
    const float* x  = (const float*)d_in[0];
    const float* Wq = (const float*)d_in[1];
    const float* Wk = (const float*)d_in[2];
    const float* Wv = (const float*)d_in[3];
    const float* Wo = (const float*)d_in[4];
    float* out = (float*)d_out;

    int seq = in_sizes[0] / DIM;  // 4096

    float* q = nullptr; float* k = nullptr; float* v = nullptr; float* attn = nullptr;
    cudaGetSymbolAddress((void**)&q, g_q);
    cudaGetSymbolAddress((void**)&k, g_k);
    cudaGetSymbolAddress((void**)&v, g_v);
    cudaGetSymbolAddress((void**)&attn, g_attn);

    dim3 gg(DIM / 128, seq / 128);
    gemm_mma<1><<<gg, 256>>>(x, Wq, q, seq);
    gemm_mma<1><<<gg, 256>>>(x, Wk, k, seq);
    gemm_mma<2><<<gg, 256>>>(x, Wv, v, seq);

    const int smem_attn = (3 * BQ * RPAD + BQ * SPAD + 3 * BQ) * sizeof(float);
    cudaFuncSetAttribute(attn_kernel, cudaFuncAttributeMaxDynamicSharedMemorySize,
                         smem_attn);
    attn_kernel<<<dim3(seq / BQ, NHEADS), 256, smem_attn>>>(q, k, v, attn, seq);

    gemm_mma<0><<<gg, 256>>>(attn, Wo, out, seq);
}

// round 8
// speedup vs baseline: 2.0250x; 1.0407x over previous
#include <cuda_runtime.h>
#include <math.h>
#include <stdint.h>

#define NHEADS 16
#define HDIM   128
#define DIM    2048
#define WIN    512
#define SEQ_MAX 4096
#define S20    20   // smem row stride (floats): conflict-free + 16B aligned
#define STAGES 4
#define NCHUNK (DIM / 16)

// ---------------- scratch ----------------
__device__ float g_q[(size_t)NHEADS * SEQ_MAX * HDIM];
__device__ float g_k[(size_t)NHEADS * SEQ_MAX * HDIM];
__device__ float g_v[(size_t)NHEADS * SEQ_MAX * HDIM];
__device__ float g_attn[(size_t)SEQ_MAX * DIM];
// tf32-pre-rounded inputs
__device__ float g_xr[(size_t)SEQ_MAX * DIM];
__device__ float g_wqr[(size_t)DIM * DIM];
__device__ float g_wkr[(size_t)DIM * DIM];
__device__ float g_wvr[(size_t)DIM * DIM];
__device__ float g_wor[(size_t)DIM * DIM];

// ---------------- helpers ----------------
__device__ __forceinline__ float tf32r(float x) {
    float y;
    asm("cvt.rna.tf32.f32 %0, %1;" : "=f"(y) : "f"(x));
    return y;
}
__device__ __forceinline__ void cpasync16(void* dst, const void* src) {
    uint32_t d = (uint32_t)__cvta_generic_to_shared(dst);
    asm volatile("cp.async.cg.shared.global [%0], [%1], 16;" :: "r"(d), "l"(src));
}
__device__ __forceinline__ void cp_commit() {
    asm volatile("cp.async.commit_group;" ::: "memory");
}
__device__ __forceinline__ void cp_wait2() {
    asm volatile("cp.async.wait_group 2;" ::: "memory");
}
__device__ __forceinline__ void mma8(float* d, const uint32_t* a, const uint32_t* b) {
    asm volatile(
        "mma.sync.aligned.m16n8k8.row.col.f32.tf32.tf32.f32 "
        "{%0,%1,%2,%3}, {%4,%5,%6,%7}, {%8,%9}, {%0,%1,%2,%3};"
        : "+f"(d[0]), "+f"(d[1]), "+f"(d[2]), "+f"(d[3])
        : "r"(a[0]), "r"(a[1]), "r"(a[2]), "r"(a[3]), "r"(b[0]), "r"(b[1]));
}

// ---------------- tf32 pre-rounding pass ----------------
__global__ void round_pass(const float* __restrict__ src, float* __restrict__ dst,
                           int n4) {
    int i = blockIdx.x * blockDim.x + threadIdx.x;
    int stride = gridDim.x * blockDim.x;
    for (; i < n4; i += stride) {
        float4 v = ((const float4*)src)[i];
        v.x = tf32r(v.x); v.y = tf32r(v.y); v.z = tf32r(v.z); v.w = tf32r(v.w);
        ((float4*)dst)[i] = v;
    }
}

// ---------------- tf32 mma.sync GEMM, cp.async 4-stage --------------------
// C = A[M,2048] @ B[2048,2048]^T. Inputs must be pre-rounded to tf32 grid.
// Tile 128x128, 8 warps (2 n x 4 m), warp tile 32(m) x 64(n).
// MODE 0: row-major C.  MODE 1: RoPE + head-major.  MODE 2: head-major.
template <int MODE>
__global__ void __launch_bounds__(256, 2)
gemm_mma(const float* __restrict__ A, const float* __restrict__ B,
         float* __restrict__ C, int M) {
    extern __shared__ float sh[];
    float* AsB = sh;                          // [STAGES][128*S20]
    float* BsB = sh + STAGES * 128 * S20;     // [STAGES][128*S20]

    const int tid = threadIdx.x, wid = tid >> 5, lane = tid & 31;
    const int g = lane >> 2, tg = lane & 3;
    const int bm = blockIdx.y * 128, bn = blockIdx.x * 128;
    const int wm = (wid >> 1) * 32, wn = (wid & 1) * 64;

    float c[2][8][4];
#pragma unroll
    for (int mt = 0; mt < 2; mt++)
#pragma unroll
        for (int nt = 0; nt < 8; nt++)
#pragma unroll
            for (int j = 0; j < 4; j++) c[mt][nt][j] = 0.f;

    const int lr = tid >> 2;           // 0..63
    const int lk = (tid & 3) << 2;     // 0,4,8,12
    const float* Ap = A + (size_t)(bm + lr) * DIM + lk;
    const float* Bp = B + (size_t)(bn + lr) * DIM + lk;

#define ISSUE(kc)                                                         \
    do {                                                                  \
        const int st_ = (kc) & (STAGES - 1);                              \
        float* a_ = AsB + st_ * 128 * S20;                                \
        float* b_ = BsB + st_ * 128 * S20;                                \
        const int ko_ = (kc) * 16;                                        \
        cpasync16(&a_[lr * S20 + lk], Ap + ko_);                          \
        cpasync16(&a_[(lr + 64) * S20 + lk], Ap + (size_t)64 * DIM + ko_);\
        cpasync16(&b_[lr * S20 + lk], Bp + ko_);                          \
        cpasync16(&b_[(lr + 64) * S20 + lk], Bp + (size_t)64 * DIM + ko_);\
    } while (0)

    ISSUE(0); cp_commit();
    ISSUE(1); cp_commit();
    ISSUE(2); cp_commit();

    for (int kc = 0; kc < NCHUNK; kc++) {
        cp_wait2();
        __syncthreads();
        if (kc + 3 < NCHUNK) ISSUE(kc + 3);
        cp_commit();

        const float* As = AsB + (kc & (STAGES - 1)) * 128 * S20;
        const float* Bs = BsB + (kc & (STAGES - 1)) * 128 * S20;
#pragma unroll
        for (int s = 0; s < 2; s++) {
            uint32_t af[2][4], bf[8][2];
#pragma unroll
            for (int mt = 0; mt < 2; mt++) {
                const float* base = &As[(wm + mt * 16) * S20 + s * 8];
                af[mt][0] = __float_as_uint(base[g * S20 + tg]);
                af[mt][1] = __float_as_uint(base[(g + 8) * S20 + tg]);
                af[mt][2] = __float_as_uint(base[g * S20 + tg + 4]);
                af[mt][3] = __float_as_uint(base[(g + 8) * S20 + tg + 4]);
            }
#pragma unroll
            for (int nt = 0; nt < 8; nt++) {
                const float* base = &Bs[(wn + nt * 8 + g) * S20 + s * 8];
                bf[nt][0] = __float_as_uint(base[tg]);
                bf[nt][1] = __float_as_uint(base[tg + 4]);
            }
#pragma unroll
            for (int mt = 0; mt < 2; mt++)
#pragma unroll
                for (int nt = 0; nt < 8; nt++)
                    mma8(c[mt][nt], af[mt], bf[nt]);
        }
    }
#undef ISSUE

    // ---- epilogue (fragment layout: rows g, g+8; cols 2*tg, 2*tg+1) ----
#pragma unroll
    for (int mt = 0; mt < 2; mt++) {
#pragma unroll
        for (int nt = 0; nt < 8; nt++) {
            const int n = bn + wn + nt * 8 + 2 * tg;
#pragma unroll
            for (int half = 0; half < 2; half++) {
                const int m = bm + wm + mt * 16 + g + half * 8;
                float x1 = c[mt][nt][half * 2];
                float x2 = c[mt][nt][half * 2 + 1];
                if (MODE == 0) {
                    *(float2*)&C[(size_t)m * DIM + n] = make_float2(x1, x2);
                } else {
                    const int head = n >> 7, d = n & 127;
                    float o1 = x1, o2 = x2;
                    if (MODE == 1) {
                        float expo = (float)d * (1.0f / 128.0f);
                        float inv_freq = (float)exp(-(double)expo * 9.210340371976184);
                        float ang = (float)m * inv_freq;
                        float sn, cs;
                        sincosf(ang, &sn, &cs);
                        o1 = x1 * cs - x2 * sn;
                        o2 = x1 * sn + x2 * cs;
                    }
                    size_t idx = ((size_t)head * M + m) * HDIM + d;
                    *(float2*)&C[idx] = make_float2(o1, o2);
                }
            }
        }
    }
}

// ---------------- windowed flash attention ----------------
#define BQ 64
#define BK 64
#define RPAD 129
#define SPAD 65

__global__ void __launch_bounds__(256, 1)
attn_kernel(const float* __restrict__ Q, const float* __restrict__ K,
            const float* __restrict__ V, float* __restrict__ O, int seq) {
    extern __shared__ float smf[];
    float* Qs  = smf;
    float* Ks  = Qs + BQ * RPAD;
    float* Vs  = Ks + BK * RPAD;
    float* Ssc = Vs + BK * RPAD;
    float* rm  = Ssc + BQ * SPAD;
    float* rl  = rm + BQ;
    float* ral = rl + BQ;

    int t = threadIdx.x;
    int head = blockIdx.y;
    int q0 = blockIdx.x * BQ;

    const float* Qh = Q + ((size_t)head * seq + q0) * HDIM;
    const float* Kh = K + (size_t)head * seq * HDIM;
    const float* Vh = V + (size_t)head * seq * HDIM;

    for (int f = t; f < BQ * HDIM / 4; f += 256) {
        float4 v = ((const float4*)Qh)[f];
        int row = f >> 5;
        int c4 = (f & 31) << 2;
        float* d = &Qs[row * RPAD + c4];
        d[0] = v.x; d[1] = v.y; d[2] = v.z; d[3] = v.w;
    }
    if (t < BQ) { rm[t] = -INFINITY; rl[t] = 0.f; }

    float acc[32];
#pragma unroll
    for (int j = 0; j < 32; j++) acc[j] = 0.f;
    int r_pv = t >> 2;
    int cph  = t & 3;

    int r0 = (t >> 4) << 2;
    int c0 = (t & 15) << 2;

    const float scale = 0.08838834764831845f;
    int kb_start = (q0 >= (WIN - 1)) ? ((q0 - (WIN - 1)) >> 6) : 0;
    int kb_end = q0 >> 6;

    for (int kb = kb_start; kb <= kb_end; ++kb) {
        int k0 = kb << 6;
        __syncthreads();
        for (int f = t; f < BK * HDIM / 4; f += 256) {
            int row = f >> 5;
            int c4 = (f & 31) << 2;
            float4 kv = ((const float4*)(Kh + (size_t)k0 * HDIM))[f];
            float* dk = &Ks[row * RPAD + c4];
            dk[0] = kv.x; dk[1] = kv.y; dk[2] = kv.z; dk[3] = kv.w;
            float4 vv = ((const float4*)(Vh + (size_t)k0 * HDIM))[f];
            float* dv = &Vs[row * RPAD + c4];
            dv[0] = vv.x; dv[1] = vv.y; dv[2] = vv.z; dv[3] = vv.w;
        }
        __syncthreads();

        float sacc[4][4];
#pragma unroll
        for (int i = 0; i < 4; i++)
#pragma unroll
            for (int j = 0; j < 4; j++) sacc[i][j] = 0.f;

#pragma unroll 4
        for (int k = 0; k < HDIM; k++) {
            float a_[4], b_[4];
#pragma unroll
            for (int i = 0; i < 4; i++) a_[i] = Qs[(r0 + i) * RPAD + k];
#pragma unroll
            for (int j = 0; j < 4; j++) b_[j] = Ks[(c0 + j) * RPAD + k];
#pragma unroll
            for (int i = 0; i < 4; i++)
#pragma unroll
                for (int j = 0; j < 4; j++) sacc[i][j] += a_[i] * b_[j];
        }
#pragma unroll
        for (int i = 0; i < 4; i++) {
            int qr = q0 + r0 + i;
#pragma unroll
            for (int j = 0; j < 4; j++) {
                int kc = k0 + c0 + j;
                bool valid = (kc <= qr) && (qr - kc < WIN);
                Ssc[(r0 + i) * SPAD + (c0 + j)] =
                    valid ? sacc[i][j] * scale : -INFINITY;
            }
        }
        __syncthreads();

        if (t < BQ) {
            int r = t;
            float mold = rm[r];
            float mb = -INFINITY;
#pragma unroll 8
            for (int c = 0; c < BK; c++) mb = fmaxf(mb, Ssc[r * SPAD + c]);
            float mnew = fmaxf(mold, mb);
            float a, ls = 0.f;
            if (mnew == -INFINITY) {
                a = 1.f;
#pragma unroll 8
                for (int c = 0; c < BK; c++) Ssc[r * SPAD + c] = 0.f;
            } else {
                a = expf(mold - mnew);
#pragma unroll 8
                for (int c = 0; c < BK; c++) {
                    float p = expf(Ssc[r * SPAD + c] - mnew);
                    Ssc[r * SPAD + c] = p;
                    ls += p;
                }
            }
            rl[r] = rl[r] * a + ls;
            rm[r] = mnew;
            ral[r] = a;
        }
        __syncthreads();

        float a = ral[r_pv];
#pragma unroll
        for (int j = 0; j < 32; j++) acc[j] *= a;
        for (int c = 0; c < BK; c++) {
            float p = Ssc[r_pv * SPAD + c];
            const float* vrow = &Vs[c * RPAD + cph];
#pragma unroll
            for (int j = 0; j < 32; j++) acc[j] += p * vrow[j * 4];
        }
    }

    // store tf32-rounded: feeds the tf32 output-projection GEMM directly
    float inv = 1.0f / rl[r_pv];
    float* Orow = O + (size_t)(q0 + r_pv) * DIM + head * HDIM + cph;
#pragma unroll
    for (int j = 0; j < 32; j++) Orow[j * 4] = tf32r(acc[j] * inv);
}

// ---------------- launch ----------------
extern "C" void kernel_launch(void* const* d_in, const int* in_sizes, int n_in,
                              void* d_out, int out_size) {
    const float* x  = (const float*)d_in[0];
    const float* Wq = (const float*)d_in[1];
    const float* Wk = (const float*)d_in[2];
    const float* Wv = (const float*)d_in[3];
    const float* Wo = (const float*)d_in[4];
    float* out = (float*)d_out;

    int seq = in_sizes[0] / DIM;  // 4096

    float *q, *k, *v, *attn, *xr, *wqr, *wkr, *wvr, *wor;
    cudaGetSymbolAddress((void**)&q, g_q);
    cudaGetSymbolAddress((void**)&k, g_k);
    cudaGetSymbolAddress((void**)&v, g_v);
    cudaGetSymbolAddress((void**)&attn, g_attn);
    cudaGetSymbolAddress((void**)&xr, g_xr);
    cudaGetSymbolAddress((void**)&wqr, g_wqr);
    cudaGetSymbolAddress((void**)&wkr, g_wkr);
    cudaGetSymbolAddress((void**)&wvr, g_wvr);
    cudaGetSymbolAddress((void**)&wor, g_wor);

    // pre-round all GEMM operands to the tf32 grid
    const int nX4 = seq * DIM / 4, nW4 = DIM * DIM / 4;
    round_pass<<<1184, 256>>>(x, xr, nX4);
    round_pass<<<1184, 256>>>(Wq, wqr, nW4);
    round_pass<<<1184, 256>>>(Wk, wkr, nW4);
    round_pass<<<1184, 256>>>(Wv, wvr, nW4);
    round_pass<<<1184, 256>>>(Wo, wor, nW4);

    const int smem_gemm = STAGES * 2 * 128 * S20 * sizeof(float);  // 81920
    cudaFuncSetAttribute(gemm_mma<0>, cudaFuncAttributeMaxDynamicSharedMemorySize, smem_gemm);
    cudaFuncSetAttribute(gemm_mma<1>, cudaFuncAttributeMaxDynamicSharedMemorySize, smem_gemm);
    cudaFuncSetAttribute(gemm_mma<2>, cudaFuncAttributeMaxDynamicSharedMemorySize, smem_gemm);

    dim3 gg(DIM / 128, seq / 128);
    gemm_mma<1><<<gg, 256, smem_gemm>>>(xr, wqr, q, seq);
    gemm_mma<1><<<gg, 256, smem_gemm>>>(xr, wkr, k, seq);
    gemm_mma<2><<<gg, 256, smem_gemm>>>(xr, wvr, v, seq);

    const int smem_attn = (3 * BQ * RPAD + BQ * SPAD + 3 * BQ) * sizeof(float);
    cudaFuncSetAttribute(attn_kernel, cudaFuncAttributeMaxDynamicSharedMemorySize,
                         smem_attn);
    attn_kernel<<<dim3(seq / BQ, NHEADS), 256, smem_attn>>>(q, k, v, attn, seq);

    gemm_mma<0><<<gg, 256, smem_gemm>>>(attn, wor, out, seq);
}

// round 10
// speedup vs baseline: 3.3255x; 1.6422x over previous
#include <cuda_runtime.h>
#include <math.h>
#include <stdint.h>

#define NHEADS 16
#define HDIM   128
#define DIM    2048
#define WIN    512
#define SEQ_MAX 4096
#define S20    20
#define STAGES 4
#define NCHUNK (DIM / 16)

// ---------------- scratch ----------------
__device__ float g_q[(size_t)NHEADS * SEQ_MAX * HDIM];   // [head][seq][d]
__device__ float g_k[(size_t)NHEADS * SEQ_MAX * HDIM];   // [head][seq][d]
__device__ float g_v[(size_t)NHEADS * SEQ_MAX * HDIM];   // [head][d][seq]  (transposed!)
__device__ float g_attn[(size_t)SEQ_MAX * DIM];
__device__ float g_xr[(size_t)SEQ_MAX * DIM];
__device__ float g_wqr[(size_t)DIM * DIM];
__device__ float g_wkr[(size_t)DIM * DIM];
__device__ float g_wvr[(size_t)DIM * DIM];
__device__ float g_wor[(size_t)DIM * DIM];

// ---------------- helpers ----------------
__device__ __forceinline__ float tf32r(float x) {
    float y;
    asm("cvt.rna.tf32.f32 %0, %1;" : "=f"(y) : "f"(x));
    return y;
}
__device__ __forceinline__ void cpasync16(void* dst, const void* src) {
    uint32_t d = (uint32_t)__cvta_generic_to_shared(dst);
    asm volatile("cp.async.cg.shared.global [%0], [%1], 16;" :: "r"(d), "l"(src));
}
__device__ __forceinline__ void cp_commit() {
    asm volatile("cp.async.commit_group;" ::: "memory");
}
__device__ __forceinline__ void cp_wait2() {
    asm volatile("cp.async.wait_group 2;" ::: "memory");
}
__device__ __forceinline__ void cp_wait0() {
    asm volatile("cp.async.wait_group 0;" ::: "memory");
}
__device__ __forceinline__ void mma8(float* d, const uint32_t* a, const uint32_t* b) {
    asm volatile(
        "mma.sync.aligned.m16n8k8.row.col.f32.tf32.tf32.f32 "
        "{%0,%1,%2,%3}, {%4,%5,%6,%7}, {%8,%9}, {%0,%1,%2,%3};"
        : "+f"(d[0]), "+f"(d[1]), "+f"(d[2]), "+f"(d[3])
        : "r"(a[0]), "r"(a[1]), "r"(a[2]), "r"(a[3]), "r"(b[0]), "r"(b[1]));
}

// ---------------- tf32 pre-rounding pass ----------------
__global__ void round_pass(const float* __restrict__ src, float* __restrict__ dst,
                           int n4) {
    int i = blockIdx.x * blockDim.x + threadIdx.x;
    int stride = gridDim.x * blockDim.x;
    for (; i < n4; i += stride) {
        float4 v = ((const float4*)src)[i];
        v.x = tf32r(v.x); v.y = tf32r(v.y); v.z = tf32r(v.z); v.w = tf32r(v.w);
        ((float4*)dst)[i] = v;
    }
}

// ---------------- tf32 mma.sync GEMM, cp.async 4-stage --------------------
// C = A[M,2048] @ B[2048,2048]^T. Inputs pre-rounded to tf32 grid.
// MODE 0: row-major C.   MODE 1: RoPE + head-major [head][m][d] (tf32r).
// MODE 2: head-major TRANSPOSED [head][d][seq] (tf32r) via smem transpose.
template <int MODE>
__global__ void __launch_bounds__(256, 2)
gemm_mma(const float* __restrict__ A, const float* __restrict__ B,
         float* __restrict__ C, int M) {
    extern __shared__ float sh[];
    float* AsB = sh;                          // [STAGES][128*S20]
    float* BsB = sh + STAGES * 128 * S20;

    const int tid = threadIdx.x, wid = tid >> 5, lane = tid & 31;
    const int g = lane >> 2, tg = lane & 3;
    const int bm = blockIdx.y * 128, bn = blockIdx.x * 128;
    const int wm = (wid >> 1) * 32, wn = (wid & 1) * 64;

    float c[2][8][4];
#pragma unroll
    for (int mt = 0; mt < 2; mt++)
#pragma unroll
        for (int nt = 0; nt < 8; nt++)
#pragma unroll
            for (int j = 0; j < 4; j++) c[mt][nt][j] = 0.f;

    const int lr = tid >> 2;
    const int lk = (tid & 3) << 2;
    const float* Ap = A + (size_t)(bm + lr) * DIM + lk;
    const float* Bp = B + (size_t)(bn + lr) * DIM + lk;

#define ISSUE(kc)                                                         \
    do {                                                                  \
        const int st_ = (kc) & (STAGES - 1);                              \
        float* a_ = AsB + st_ * 128 * S20;                                \
        float* b_ = BsB + st_ * 128 * S20;                                \
        const int ko_ = (kc) * 16;                                        \
        cpasync16(&a_[lr * S20 + lk], Ap + ko_);                          \
        cpasync16(&a_[(lr + 64) * S20 + lk], Ap + (size_t)64 * DIM + ko_);\
        cpasync16(&b_[lr * S20 + lk], Bp + ko_);                          \
        cpasync16(&b_[(lr + 64) * S20 + lk], Bp + (size_t)64 * DIM + ko_);\
    } while (0)

    ISSUE(0); cp_commit();
    ISSUE(1); cp_commit();
    ISSUE(2); cp_commit();

    for (int kc = 0; kc < NCHUNK; kc++) {
        cp_wait2();
        __syncthreads();
        if (kc + 3 < NCHUNK) ISSUE(kc + 3);
        cp_commit();

        const float* As = AsB + (kc & (STAGES - 1)) * 128 * S20;
        const float* Bs = BsB + (kc & (STAGES - 1)) * 128 * S20;
#pragma unroll
        for (int s = 0; s < 2; s++) {
            uint32_t af[2][4], bf[8][2];
#pragma unroll
            for (int mt = 0; mt < 2; mt++) {
                const float* base = &As[(wm + mt * 16) * S20 + s * 8];
                af[mt][0] = __float_as_uint(base[g * S20 + tg]);
                af[mt][1] = __float_as_uint(base[(g + 8) * S20 + tg]);
                af[mt][2] = __float_as_uint(base[g * S20 + tg + 4]);
                af[mt][3] = __float_as_uint(base[(g + 8) * S20 + tg + 4]);
            }
#pragma unroll
            for (int nt = 0; nt < 8; nt++) {
                const float* base = &Bs[(wn + nt * 8 + g) * S20 + s * 8];
                bf[nt][0] = __float_as_uint(base[tg]);
                bf[nt][1] = __float_as_uint(base[tg + 4]);
            }
#pragma unroll
            for (int mt = 0; mt < 2; mt++)
#pragma unroll
                for (int nt = 0; nt < 8; nt++)
                    mma8(c[mt][nt], af[mt], bf[nt]);
        }
    }
#undef ISSUE

    if (MODE == 2) {
        // transpose through smem, store as [head][d][seq]
        __syncthreads();   // everyone done with pipeline buffers
        float* Ct = sh;    // 128 x 130
#pragma unroll
        for (int mt = 0; mt < 2; mt++)
#pragma unroll
            for (int nt = 0; nt < 8; nt++) {
                const int n = wn + nt * 8 + 2 * tg;
#pragma unroll
                for (int half = 0; half < 2; half++) {
                    const int m = wm + mt * 16 + g + half * 8;
                    *(float2*)&Ct[m * 130 + n] =
                        make_float2(c[mt][nt][half * 2], c[mt][nt][half * 2 + 1]);
                }
            }
        __syncthreads();
        const int head = bn >> 7;
        const int n = tid >> 1;             // 0..127 (= d)
        const int mh = (tid & 1) * 64;
        float* dst = C + (size_t)head * HDIM * M + (size_t)n * M + bm + mh;
#pragma unroll 4
        for (int i = 0; i < 64; i += 4) {
            float4 w;
            w.x = tf32r(Ct[(mh + i + 0) * 130 + n]);
            w.y = tf32r(Ct[(mh + i + 1) * 130 + n]);
            w.z = tf32r(Ct[(mh + i + 2) * 130 + n]);
            w.w = tf32r(Ct[(mh + i + 3) * 130 + n]);
            *(float4*)(dst + i) = w;
        }
        return;
    }

#pragma unroll
    for (int mt = 0; mt < 2; mt++) {
#pragma unroll
        for (int nt = 0; nt < 8; nt++) {
            const int n = bn + wn + nt * 8 + 2 * tg;
#pragma unroll
            for (int half = 0; half < 2; half++) {
                const int m = bm + wm + mt * 16 + g + half * 8;
                float x1 = c[mt][nt][half * 2];
                float x2 = c[mt][nt][half * 2 + 1];
                if (MODE == 0) {
                    *(float2*)&C[(size_t)m * DIM + n] = make_float2(x1, x2);
                } else {
                    const int head = n >> 7, d = n & 127;
                    float expo = (float)d * (1.0f / 128.0f);
                    float inv_freq = (float)exp(-(double)expo * 9.210340371976184);
                    float ang = (float)m * inv_freq;
                    float sn, cs;
                    sincosf(ang, &sn, &cs);
                    float o1 = tf32r(x1 * cs - x2 * sn);
                    float o2 = tf32r(x1 * sn + x2 * cs);
                    size_t idx = ((size_t)head * M + m) * HDIM + d;
                    *(float2*)&C[idx] = make_float2(o1, o2);
                }
            }
        }
    }
}

// ---------------- tensor-core windowed flash attention --------------------
// 4 warps, each owns 16 query rows. Q regs, K/Vt via cp.async, P via smem.
#define KS_STR 132
#define VT_STR 68
#define SS_STR 68
#define AT_SMEM ((64 * KS_STR + 128 * VT_STR + 64 * SS_STR) * 4)

__global__ void __launch_bounds__(128, 2)
attn_mma(const float* __restrict__ Q, const float* __restrict__ K,
         const float* __restrict__ Vt, float* __restrict__ O, int seq) {
    extern __shared__ float sf[];
    float* Ks  = sf;                       // 64 x KS_STR
    float* Vs  = Ks + 64 * KS_STR;         // 128 x VT_STR (d-major)
    float* Ssc = Vs + 128 * VT_STR;        // 64 x SS_STR

    const int t = threadIdx.x, wid = t >> 5, lane = t & 31;
    const int g = lane >> 2, tg = lane & 3;
    const int head = blockIdx.y;
    const int q0 = blockIdx.x * 64;
    const int wr = wid * 16;

    // ---- stage Q into Ks buffer, load fragments to regs ----
    const float* Qh = Q + ((size_t)head * seq + q0) * HDIM;
    for (int f = t; f < 2048; f += 128) {
        int row = f >> 5, c4 = (f & 31) << 2;
        *(float4*)&Ks[row * KS_STR + c4] = *(const float4*)(Qh + row * HDIM + c4);
    }
    __syncthreads();
    uint32_t qf[16][4];
#pragma unroll
    for (int ks = 0; ks < 16; ks++) {
        const float* base = &Ks[(wr + g) * KS_STR + ks * 8];
        qf[ks][0] = __float_as_uint(base[tg]);
        qf[ks][1] = __float_as_uint(base[8 * KS_STR + tg]);
        qf[ks][2] = __float_as_uint(base[tg + 4]);
        qf[ks][3] = __float_as_uint(base[8 * KS_STR + tg + 4]);
    }
    __syncthreads();

    float o[16][4];
#pragma unroll
    for (int dt = 0; dt < 16; dt++)
#pragma unroll
        for (int j = 0; j < 4; j++) o[dt][j] = 0.f;
    float m0 = -INFINITY, m1 = -INFINITY, l0 = 0.f, l1 = 0.f;

    const float scale = 0.08838834764831845f;
    const int r0g = q0 + wr + g, r1g = r0g + 8;
    const int kbs = (q0 >= (WIN - 1)) ? ((q0 - (WIN - 1)) >> 6) : 0;
    const int kbe = q0 >> 6;

    const float* Kb = K + ((size_t)head * seq) * HDIM;
    const float* Vb = Vt + (size_t)head * HDIM * seq;

    for (int kb = kbs; kb <= kbe; kb++) {
        const int k0 = kb << 6;
        // ---- load K (seq-major) and V (d-major) tiles ----
        for (int f = t; f < 2048; f += 128) {
            int row = f >> 5, c4 = (f & 31) << 2;
            cpasync16(&Ks[row * KS_STR + c4], Kb + (size_t)(k0 + row) * HDIM + c4);
        }
        for (int f = t; f < 2048; f += 128) {
            int row = f >> 4, c4 = (f & 15) << 2;
            cpasync16(&Vs[row * VT_STR + c4], Vb + (size_t)row * seq + k0 + c4);
        }
        cp_commit();
        cp_wait0();
        __syncthreads();

        // ---- S = Q @ K^T ----
        float s[8][4];
#pragma unroll
        for (int nt = 0; nt < 8; nt++)
#pragma unroll
            for (int j = 0; j < 4; j++) s[nt][j] = 0.f;
#pragma unroll
        for (int ks = 0; ks < 16; ks++) {
            uint32_t bf[8][2];
#pragma unroll
            for (int nt = 0; nt < 8; nt++) {
                const float* base = &Ks[(nt * 8 + g) * KS_STR + ks * 8];
                bf[nt][0] = __float_as_uint(base[tg]);
                bf[nt][1] = __float_as_uint(base[tg + 4]);
            }
#pragma unroll
            for (int nt = 0; nt < 8; nt++)
                mma8(s[nt], qf[ks], bf[nt]);
        }

        // ---- scale + mask ----
        const bool needmask = (kb == kbs) || (kb == kbe);
#pragma unroll
        for (int nt = 0; nt < 8; nt++) {
            const int c = k0 + nt * 8 + 2 * tg;
#pragma unroll
            for (int j = 0; j < 4; j++) s[nt][j] *= scale;
            if (needmask) {
                const int c1 = c + 1;
                if (!((c <= r0g) && (r0g - c < WIN)))  s[nt][0] = -INFINITY;
                if (!((c1 <= r0g) && (r0g - c1 < WIN))) s[nt][1] = -INFINITY;
                if (!((c <= r1g) && (r1g - c < WIN)))  s[nt][2] = -INFINITY;
                if (!((c1 <= r1g) && (r1g - c1 < WIN))) s[nt][3] = -INFINITY;
            }
        }

        // ---- online softmax (rows r0g, r1g; quad reduce over tg lanes) ----
        float mb0 = -INFINITY, mb1 = -INFINITY;
#pragma unroll
        for (int nt = 0; nt < 8; nt++) {
            mb0 = fmaxf(mb0, fmaxf(s[nt][0], s[nt][1]));
            mb1 = fmaxf(mb1, fmaxf(s[nt][2], s[nt][3]));
        }
        mb0 = fmaxf(mb0, __shfl_xor_sync(0xffffffffu, mb0, 1));
        mb0 = fmaxf(mb0, __shfl_xor_sync(0xffffffffu, mb0, 2));
        mb1 = fmaxf(mb1, __shfl_xor_sync(0xffffffffu, mb1, 1));
        mb1 = fmaxf(mb1, __shfl_xor_sync(0xffffffffu, mb1, 2));

        float mn0 = fmaxf(m0, mb0), mn1 = fmaxf(m1, mb1);
        float ms0 = (mn0 == -INFINITY) ? 0.f : mn0;
        float ms1 = (mn1 == -INFINITY) ? 0.f : mn1;
        float a0 = __expf(m0 - ms0), a1 = __expf(m1 - ms1);
        if (m0 == -INFINITY) a0 = 0.f;
        if (m1 == -INFINITY) a1 = 0.f;

        float ls0 = 0.f, ls1 = 0.f;
#pragma unroll
        for (int nt = 0; nt < 8; nt++) {
            s[nt][0] = __expf(s[nt][0] - ms0);
            s[nt][1] = __expf(s[nt][1] - ms0);
            s[nt][2] = __expf(s[nt][2] - ms1);
            s[nt][3] = __expf(s[nt][3] - ms1);
            ls0 += s[nt][0] + s[nt][1];
            ls1 += s[nt][2] + s[nt][3];
        }
        ls0 += __shfl_xor_sync(0xffffffffu, ls0, 1);
        ls0 += __shfl_xor_sync(0xffffffffu, ls0, 2);
        ls1 += __shfl_xor_sync(0xffffffffu, ls1, 1);
        ls1 += __shfl_xor_sync(0xffffffffu, ls1, 2);
        l0 = l0 * a0 + ls0;
        l1 = l1 * a1 + ls1;
        m0 = mn0; m1 = mn1;

        // ---- write P (tf32) to Ssc; rescale O ----
#pragma unroll
        for (int nt = 0; nt < 8; nt++) {
            const int cc = nt * 8 + 2 * tg;
            *(float2*)&Ssc[(wr + g) * SS_STR + cc] =
                make_float2(tf32r(s[nt][0]), tf32r(s[nt][1]));
            *(float2*)&Ssc[(wr + g + 8) * SS_STR + cc] =
                make_float2(tf32r(s[nt][2]), tf32r(s[nt][3]));
        }
#pragma unroll
        for (int dt = 0; dt < 16; dt++) {
            o[dt][0] *= a0; o[dt][1] *= a0;
            o[dt][2] *= a1; o[dt][3] *= a1;
        }
        __syncwarp();

        // ---- O += P @ V  (A from Ssc, B from d-major Vs) ----
#pragma unroll
        for (int kc = 0; kc < 8; kc++) {
            uint32_t af[4];
            const float* ab = &Ssc[(wr + g) * SS_STR + kc * 8];
            af[0] = __float_as_uint(ab[tg]);
            af[1] = __float_as_uint(ab[8 * SS_STR + tg]);
            af[2] = __float_as_uint(ab[tg + 4]);
            af[3] = __float_as_uint(ab[8 * SS_STR + tg + 4]);
#pragma unroll
            for (int dt = 0; dt < 16; dt++) {
                uint32_t bf[2];
                const float* bb = &Vs[(dt * 8 + g) * VT_STR + kc * 8];
                bf[0] = __float_as_uint(bb[tg]);
                bf[1] = __float_as_uint(bb[tg + 4]);
                mma8(o[dt], af, bf);
            }
        }
        __syncthreads();
    }

    // ---- normalize + store (tf32r: feeds the Wo GEMM) ----
    const float i0 = 1.f / l0, i1 = 1.f / l1;
#pragma unroll
    for (int dt = 0; dt < 16; dt++) {
        const int col = head * HDIM + dt * 8 + 2 * tg;
        *(float2*)&O[(size_t)r0g * DIM + col] =
            make_float2(tf32r(o[dt][0] * i0), tf32r(o[dt][1] * i0));
        *(float2*)&O[(size_t)r1g * DIM + col] =
            make_float2(tf32r(o[dt][2] * i1), tf32r(o[dt][3] * i1));
    }
}

// ---------------- launch ----------------
extern "C" void kernel_launch(void* const* d_in, const int* in_sizes, int n_in,
                              void* d_out, int out_size) {
    const float* x  = (const float*)d_in[0];
    const float* Wq = (const float*)d_in[1];
    const float* Wk = (const float*)d_in[2];
    const float* Wv = (const float*)d_in[3];
    const float* Wo = (const float*)d_in[4];
    float* out = (float*)d_out;

    int seq = in_sizes[0] / DIM;  // 4096

    float *q, *k, *v, *attn, *xr, *wqr, *wkr, *wvr, *wor;
    cudaGetSymbolAddress((void**)&q, g_q);
    cudaGetSymbolAddress((void**)&k, g_k);
    cudaGetSymbolAddress((void**)&v, g_v);
    cudaGetSymbolAddress((void**)&attn, g_attn);
    cudaGetSymbolAddress((void**)&xr, g_xr);
    cudaGetSymbolAddress((void**)&wqr, g_wqr);
    cudaGetSymbolAddress((void**)&wkr, g_wkr);
    cudaGetSymbolAddress((void**)&wvr, g_wvr);
    cudaGetSymbolAddress((void**)&wor, g_wor);

    const int nX4 = seq * DIM / 4, nW4 = DIM * DIM / 4;
    round_pass<<<1184, 256>>>(x, xr, nX4);
    round_pass<<<1184, 256>>>(Wq, wqr, nW4);
    round_pass<<<1184, 256>>>(Wk, wkr, nW4);
    round_pass<<<1184, 256>>>(Wv, wvr, nW4);
    round_pass<<<1184, 256>>>(Wo, wor, nW4);

    const int smem_gemm = STAGES * 2 * 128 * S20 * sizeof(float);  // 81920
    cudaFuncSetAttribute(gemm_mma<0>, cudaFuncAttributeMaxDynamicSharedMemorySize, smem_gemm);
    cudaFuncSetAttribute(gemm_mma<1>, cudaFuncAttributeMaxDynamicSharedMemorySize, smem_gemm);
    cudaFuncSetAttribute(gemm_mma<2>, cudaFuncAttributeMaxDynamicSharedMemorySize, smem_gemm);

    dim3 gg(DIM / 128, seq / 128);
    gemm_mma<1><<<gg, 256, smem_gemm>>>(xr, wqr, q, seq);
    gemm_mma<1><<<gg, 256, smem_gemm>>>(xr, wkr, k, seq);
    gemm_mma<2><<<gg, 256, smem_gemm>>>(xr, wvr, v, seq);

    cudaFuncSetAttribute(attn_mma, cudaFuncAttributeMaxDynamicSharedMemorySize, AT_SMEM);
    attn_mma<<<dim3(seq / 64, NHEADS), 128, AT_SMEM>>>(q, k, v, attn, seq);

    gemm_mma<0><<<gg, 256, smem_gemm>>>(attn, wor, out, seq);
}

// round 15
// speedup vs baseline: 5.3620x; 1.6124x over previous
#include <cuda_runtime.h>
#include <cuda_fp16.h>
#include <math.h>
#include <stdint.h>

#define NHEADS 16
#define HDIM   128
#define DIM    2048
#define WIN    512
#define SEQ_MAX 4096

// ---------------- scratch (fp16) ----------------
__device__ __half g_xh[(size_t)SEQ_MAX * DIM];
__device__ __half g_wqh[(size_t)DIM * DIM];
__device__ __half g_wkh[(size_t)DIM * DIM];
__device__ __half g_wvh[(size_t)DIM * DIM];
__device__ __half g_woh[(size_t)DIM * DIM];
__device__ __half g_q[(size_t)NHEADS * SEQ_MAX * HDIM];   // [head][seq][d]
__device__ __half g_k[(size_t)NHEADS * SEQ_MAX * HDIM];   // [head][seq][d]
__device__ __half g_v[(size_t)NHEADS * SEQ_MAX * HDIM];   // [head][d][seq] transposed
__device__ __half g_attn[(size_t)SEQ_MAX * DIM];

// ---------------- helpers ----------------
__device__ __forceinline__ void cpasync16(void* dst, const void* src) {
    uint32_t d = (uint32_t)__cvta_generic_to_shared(dst);
    asm volatile("cp.async.cg.shared.global [%0], [%1], 16;" :: "r"(d), "l"(src));
}
__device__ __forceinline__ void cp_commit() {
    asm volatile("cp.async.commit_group;" ::: "memory");
}
__device__ __forceinline__ void cp_wait2() {
    asm volatile("cp.async.wait_group 2;" ::: "memory");
}
__device__ __forceinline__ void cp_wait1() {
    asm volatile("cp.async.wait_group 1;" ::: "memory");
}
__device__ __forceinline__ void cp_wait0() {
    asm volatile("cp.async.wait_group 0;" ::: "memory");
}
__device__ __forceinline__ void mma16(float* d, const uint32_t* a, const uint32_t* b) {
    asm volatile(
        "mma.sync.aligned.m16n8k16.row.col.f32.f16.f16.f32 "
        "{%0,%1,%2,%3}, {%4,%5,%6,%7}, {%8,%9}, {%0,%1,%2,%3};"
        : "+f"(d[0]), "+f"(d[1]), "+f"(d[2]), "+f"(d[3])
        : "r"(a[0]), "r"(a[1]), "r"(a[2]), "r"(a[3]), "r"(b[0]), "r"(b[1]));
}

// ---------------- fp32 -> fp16 conversion pass ----------------
__global__ void conv_h(const float* __restrict__ src, __half* __restrict__ dst,
                       int n4) {
    int i = blockIdx.x * blockDim.x + threadIdx.x;
    int stride = gridDim.x * blockDim.x;
    for (; i < n4; i += stride) {
        float4 v = ((const float4*)src)[i];
        __half2 h0 = __floats2half2_rn(v.x, v.y);
        __half2 h1 = __floats2half2_rn(v.z, v.w);
        uint2 o;
        o.x = *(uint32_t*)&h0;
        o.y = *(uint32_t*)&h1;
        ((uint2*)dst)[i] = o;
    }
}

// ---------------- fp16 mma GEMM: C = A[M,2048] @ B[2048,2048]^T -----------
// Tile 128x128, 8 warps (2n x 4m), warp tile 32x64. K chunk = 32, 4-stage.
// MODE 0: fp32 row-major C.  MODE 1: RoPE -> fp16 [head][m][d].
// MODE 2: fp16 TRANSPOSED [head][d][seq].
#define HS 40
#define KC 32
#define NCH (DIM / KC)
#define GSTAGES 4

template <int MODE>
__global__ void __launch_bounds__(256, 2)
gemm_h(const __half* __restrict__ A, const __half* __restrict__ B,
       void* __restrict__ Cv, int M) {
    extern __shared__ __half sh2[];
    __half* AsB = sh2;                       // [4][128*HS]
    __half* BsB = sh2 + GSTAGES * 128 * HS;

    const int tid = threadIdx.x, wid = tid >> 5, lane = tid & 31;
    const int g = lane >> 2, tg = lane & 3;
    const int bm = blockIdx.y * 128, bn = blockIdx.x * 128;
    const int wm = (wid >> 1) * 32, wn = (wid & 1) * 64;

    float c[2][8][4];
#pragma unroll
    for (int mt = 0; mt < 2; mt++)
#pragma unroll
        for (int nt = 0; nt < 8; nt++)
#pragma unroll
            for (int j = 0; j < 4; j++) c[mt][nt][j] = 0.f;

    const int ar = tid >> 1;            // 0..127
    const int a8 = (tid & 1) * 16;      // halves offset 0 / 16
    const __half* Ap = A + (size_t)(bm + ar) * DIM + a8;
    const __half* Bp = B + (size_t)(bn + ar) * DIM + a8;

#define GISSUE(kc)                                                   \
    do {                                                             \
        const int st_ = (kc) & (GSTAGES - 1);                        \
        __half* a_ = AsB + st_ * 128 * HS + ar * HS + a8;            \
        __half* b_ = BsB + st_ * 128 * HS + ar * HS + a8;            \
        const int ko_ = (kc) * KC;                                   \
        cpasync16(a_, Ap + ko_);                                     \
        cpasync16(a_ + 8, Ap + ko_ + 8);                             \
        cpasync16(b_, Bp + ko_);                                     \
        cpasync16(b_ + 8, Bp + ko_ + 8);                             \
    } while (0)

    GISSUE(0); cp_commit();
    GISSUE(1); cp_commit();
    GISSUE(2); cp_commit();

    for (int kc = 0; kc < NCH; kc++) {
        cp_wait2();
        __syncthreads();
        if (kc + 3 < NCH) GISSUE(kc + 3);
        cp_commit();

        const __half* As = AsB + (kc & (GSTAGES - 1)) * 128 * HS;
        const __half* Bs = BsB + (kc & (GSTAGES - 1)) * 128 * HS;
#pragma unroll
        for (int s = 0; s < 2; s++) {
            uint32_t af[2][4], bf[8][2];
#pragma unroll
            for (int mt = 0; mt < 2; mt++) {
                const __half* base = &As[(wm + mt * 16 + g) * HS + s * 16];
                af[mt][0] = *(const uint32_t*)&base[2 * tg];
                af[mt][1] = *(const uint32_t*)&base[8 * HS + 2 * tg];
                af[mt][2] = *(const uint32_t*)&base[2 * tg + 8];
                af[mt][3] = *(const uint32_t*)&base[8 * HS + 2 * tg + 8];
            }
#pragma unroll
            for (int nt = 0; nt < 8; nt++) {
                const __half* base = &Bs[(wn + nt * 8 + g) * HS + s * 16];
                bf[nt][0] = *(const uint32_t*)&base[2 * tg];
                bf[nt][1] = *(const uint32_t*)&base[2 * tg + 8];
            }
#pragma unroll
            for (int mt = 0; mt < 2; mt++)
#pragma unroll
                for (int nt = 0; nt < 8; nt++)
                    mma16(c[mt][nt], af[mt], bf[nt]);
        }
    }
#undef GISSUE

    if (MODE == 2) {
        // transpose via smem -> [head][d][seq] fp16
        cp_wait0();
        __syncthreads();
        float* Ct = (float*)sh2;   // 128 x 130 floats = 66560 B <= 81920
#pragma unroll
        for (int mt = 0; mt < 2; mt++)
#pragma unroll
            for (int nt = 0; nt < 8; nt++) {
                const int n = wn + nt * 8 + 2 * tg;
#pragma unroll
                for (int half_ = 0; half_ < 2; half_++) {
                    const int m = wm + mt * 16 + g + half_ * 8;
                    *(float2*)&Ct[m * 130 + n] =
                        make_float2(c[mt][nt][half_ * 2], c[mt][nt][half_ * 2 + 1]);
                }
            }
        __syncthreads();
        const int head = bn >> 7;
        const int d = tid >> 1;             // 0..127
        const int mh = (tid & 1) * 64;
        __half* dst = (__half*)Cv + (size_t)head * HDIM * M + (size_t)d * M + bm + mh;
#pragma unroll 8
        for (int i = 0; i < 64; i += 2) {
            __half2 h = __floats2half2_rn(Ct[(mh + i) * 130 + d],
                                          Ct[(mh + i + 1) * 130 + d]);
            *(__half2*)(dst + i) = h;
        }
        return;
    }

#pragma unroll
    for (int mt = 0; mt < 2; mt++) {
#pragma unroll
        for (int nt = 0; nt < 8; nt++) {
            const int n = bn + wn + nt * 8 + 2 * tg;
#pragma unroll
            for (int half_ = 0; half_ < 2; half_++) {
                const int m = bm + wm + mt * 16 + g + half_ * 8;
                float x1 = c[mt][nt][half_ * 2];
                float x2 = c[mt][nt][half_ * 2 + 1];
                if (MODE == 0) {
                    *(float2*)&((float*)Cv)[(size_t)m * DIM + n] = make_float2(x1, x2);
                } else {
                    const int head = n >> 7, d = n & 127;
                    float expo = (float)d * (1.0f / 128.0f);
                    float inv_freq = (float)exp(-(double)expo * 9.210340371976184);
                    float ang = (float)m * inv_freq;
                    float sn, cs;
                    sincosf(ang, &sn, &cs);
                    float o1 = x1 * cs - x2 * sn;
                    float o2 = x1 * sn + x2 * cs;
                    size_t idx = ((size_t)head * M + m) * HDIM + d;
                    *(__half2*)&((__half*)Cv)[idx] = __floats2half2_rn(o1, o2);
                }
            }
        }
    }
}

// ---------------- fp16 flash attention, BQ=128, double-buffered -----------
#define AQ 128
#define KSTR 136
#define VSTR 72
#define SSTR 72
#define AT_SMEM ((2 * 64 * KSTR + 2 * 128 * VSTR + 128 * SSTR) * 2)
#define LOG2E 1.4426950408889634f

__global__ void __launch_bounds__(256, 1)
attn_h(const __half* __restrict__ Q, const __half* __restrict__ K,
       const __half* __restrict__ Vt, __half* __restrict__ O, int seq) {
    extern __shared__ __half hs[];
    __half* Ks0 = hs;
    __half* Ks1 = hs + 64 * KSTR;
    __half* Vs0 = hs + 2 * 64 * KSTR;
    __half* Vs1 = Vs0 + 128 * VSTR;
    __half* Ssc = Vs0 + 2 * 128 * VSTR;

    const int t = threadIdx.x, wid = t >> 5, lane = t & 31;
    const int g = lane >> 2, tg = lane & 3;
    const int head = blockIdx.y, q0 = blockIdx.x * AQ;
    const int wr = wid * 16;

    // ---- stage Q (128 x 128 half) into the Ks area ----
    const __half* Qh = Q + ((size_t)head * seq + q0) * HDIM;
    {
        int row = t >> 1;
        int sb = (t & 1) * 8;
#pragma unroll
        for (int i = 0; i < 8; i++) {
            int seg = sb + i;
            cpasync16(&hs[row * KSTR + seg * 8], Qh + (size_t)row * HDIM + seg * 8);
        }
    }
    cp_commit(); cp_wait0();
    __syncthreads();

    uint32_t qf[8][4];
#pragma unroll
    for (int s = 0; s < 8; s++) {
        const __half* base = &hs[(wr + g) * KSTR + s * 16];
        qf[s][0] = *(const uint32_t*)&base[2 * tg];
        qf[s][1] = *(const uint32_t*)&base[8 * KSTR + 2 * tg];
        qf[s][2] = *(const uint32_t*)&base[2 * tg + 8];
        qf[s][3] = *(const uint32_t*)&base[8 * KSTR + 2 * tg + 8];
    }
    __syncthreads();

    float o[16][4];
#pragma unroll
    for (int dt = 0; dt < 16; dt++)
#pragma unroll
        for (int j = 0; j < 4; j++) o[dt][j] = 0.f;
    float m0 = -INFINITY, m1 = -INFINITY, l0 = 0.f, l1 = 0.f;

    const float scale = 0.08838834764831845f;
    const int r0g = q0 + wr + g, r1g = r0g + 8;
    const int r_lo = q0 + wr, r_hi = r_lo + 15;

    const int kbs = (q0 >= WIN) ? ((q0 - WIN + 1) >> 6) : 0;
    const int kbe = (q0 + AQ - 1) >> 6;
    const int kb_lo_w = (r_lo >= WIN) ? ((r_lo - WIN + 1) >> 6) : 0;
    const int kb_hi_w = r_hi >> 6;

    const __half* Kb = K + (size_t)head * seq * HDIM;
    const __half* Vb = Vt + (size_t)head * HDIM * seq;

    const int krow = t >> 2, ksb = (t & 3) * 4;
    const int vrow = t >> 1, vsb = (t & 1) * 4;

#define AKV(kb_, ks_, vs_)                                                         \
    do {                                                                           \
        const int k0_ = (kb_) << 6;                                                \
        _Pragma("unroll")                                                          \
        for (int i = 0; i < 4; i++) {                                              \
            int seg = ksb + i;                                                     \
            cpasync16(&(ks_)[krow * KSTR + seg * 8],                               \
                      Kb + (size_t)(k0_ + krow) * HDIM + seg * 8);                 \
        }                                                                          \
        _Pragma("unroll")                                                          \
        for (int i = 0; i < 4; i++) {                                              \
            int seg = vsb + i;                                                     \
            cpasync16(&(vs_)[vrow * VSTR + seg * 8],                               \
                      Vb + (size_t)vrow * seq + k0_ + seg * 8);                    \
        }                                                                          \
    } while (0)

    AKV(kbs, Ks0, Vs0);
    cp_commit();

    for (int kb = kbs; kb <= kbe; kb++) {
        const int b = (kb - kbs) & 1;
        __half* Ksc = b ? Ks1 : Ks0;
        __half* Vsc = b ? Vs1 : Vs0;
        if (kb < kbe) {
            if (b) AKV(kb + 1, Ks0, Vs0); else AKV(kb + 1, Ks1, Vs1);
            cp_commit();
            cp_wait1();
        } else {
            cp_wait0();
        }
        __syncthreads();

        if (kb >= kb_lo_w && kb <= kb_hi_w) {
            const int k0 = kb << 6;

            // ---- S = Q @ K^T ----
            float s[8][4];
#pragma unroll
            for (int nt = 0; nt < 8; nt++)
#pragma unroll
                for (int j = 0; j < 4; j++) s[nt][j] = 0.f;
#pragma unroll
            for (int ks = 0; ks < 8; ks++) {
                uint32_t bf[8][2];
#pragma unroll
                for (int nt = 0; nt < 8; nt++) {
                    const __half* base = &Ksc[(nt * 8 + g) * KSTR + ks * 16];
                    bf[nt][0] = *(const uint32_t*)&base[2 * tg];
                    bf[nt][1] = *(const uint32_t*)&base[2 * tg + 8];
                }
#pragma unroll
                for (int nt = 0; nt < 8; nt++)
                    mma16(s[nt], qf[ks], bf[nt]);
            }

            // ---- scale + mask ----
            const bool needmask = !((k0 + 63 <= r_lo) && (r_hi - k0 < WIN));
#pragma unroll
            for (int nt = 0; nt < 8; nt++) {
                const int cc = k0 + nt * 8 + 2 * tg;
#pragma unroll
                for (int j = 0; j < 4; j++) s[nt][j] *= scale;
                if (needmask) {
                    const int c1 = cc + 1;
                    if (!((cc <= r0g) && (r0g - cc < WIN))) s[nt][0] = -INFINITY;
                    if (!((c1 <= r0g) && (r0g - c1 < WIN))) s[nt][1] = -INFINITY;
                    if (!((cc <= r1g) && (r1g - cc < WIN))) s[nt][2] = -INFINITY;
                    if (!((c1 <= r1g) && (r1g - c1 < WIN))) s[nt][3] = -INFINITY;
                }
            }

            // ---- online softmax ----
            float mb0 = -INFINITY, mb1 = -INFINITY;
#pragma unroll
            for (int nt = 0; nt < 8; nt++) {
                mb0 = fmaxf(mb0, fmaxf(s[nt][0], s[nt][1]));
                mb1 = fmaxf(mb1, fmaxf(s[nt][2], s[nt][3]));
            }
            mb0 = fmaxf(mb0, __shfl_xor_sync(0xffffffffu, mb0, 1));
            mb0 = fmaxf(mb0, __shfl_xor_sync(0xffffffffu, mb0, 2));
            mb1 = fmaxf(mb1, __shfl_xor_sync(0xffffffffu, mb1, 1));
            mb1 = fmaxf(mb1, __shfl_xor_sync(0xffffffffu, mb1, 2));

            float mn0 = fmaxf(m0, mb0), mn1 = fmaxf(m1, mb1);
            float ms0 = (mn0 == -INFINITY) ? 0.f : mn0;
            float ms1 = (mn1 == -INFINITY) ? 0.f : mn1;
            float a0 = __expf(m0 - ms0), a1 = __expf(m1 - ms1);
            if (m0 == -INFINITY) a0 = 0.f;
            if (m1 == -INFINITY) a1 = 0.f;

            float ls0 = 0.f, ls1 = 0.f;
#pragma unroll
            for (int nt = 0; nt < 8; nt++) {
                const int cc = nt * 8 + 2 * tg;
                __half2 lo = __floats2half2_rn((s[nt][0] - ms0) * LOG2E,
                                               (s[nt][1] - ms0) * LOG2E);
                __half2 hi = __floats2half2_rn((s[nt][2] - ms1) * LOG2E,
                                               (s[nt][3] - ms1) * LOG2E);
                lo = h2exp2(lo);
                hi = h2exp2(hi);
                *(__half2*)&Ssc[(wr + g) * SSTR + cc] = lo;
                *(__half2*)&Ssc[(wr + g + 8) * SSTR + cc] = hi;
                float2 f0 = __half22float2(lo), f1 = __half22float2(hi);
                ls0 += f0.x + f0.y;
                ls1 += f1.x + f1.y;
            }
            ls0 += __shfl_xor_sync(0xffffffffu, ls0, 1);
            ls0 += __shfl_xor_sync(0xffffffffu, ls0, 2);
            ls1 += __shfl_xor_sync(0xffffffffu, ls1, 1);
            ls1 += __shfl_xor_sync(0xffffffffu, ls1, 2);
            l0 = l0 * a0 + ls0;
            l1 = l1 * a1 + ls1;
            m0 = mn0; m1 = mn1;

#pragma unroll
            for (int dt = 0; dt < 16; dt++) {
                o[dt][0] *= a0; o[dt][1] *= a0;
                o[dt][2] *= a1; o[dt][3] *= a1;
            }
            __syncwarp();

            // ---- O += P @ V ----
#pragma unroll
            for (int kc = 0; kc < 4; kc++) {
                uint32_t af[4];
                const __half* ab = &Ssc[(wr + g) * SSTR + kc * 16];
                af[0] = *(const uint32_t*)&ab[2 * tg];
                af[1] = *(const uint32_t*)&ab[8 * SSTR + 2 * tg];
                af[2] = *(const uint32_t*)&ab[2 * tg + 8];
                af[3] = *(const uint32_t*)&ab[8 * SSTR + 2 * tg + 8];
#pragma unroll
                for (int dt = 0; dt < 16; dt++) {
                    uint32_t bf[2];
                    const __half* bb = &Vsc[(dt * 8 + g) * VSTR + kc * 16];
                    bf[0] = *(const uint32_t*)&bb[2 * tg];
                    bf[1] = *(const uint32_t*)&bb[2 * tg + 8];
                    mma16(o[dt], af, bf);
                }
            }
        }
        __syncthreads();
    }
#undef AKV

    // ---- normalize + store fp16 [seq][DIM] ----
    const float i0 = 1.f / l0, i1 = 1.f / l1;
#pragma unroll
    for (int dt = 0; dt < 16; dt++) {
        const int col = head * HDIM + dt * 8 + 2 * tg;
        *(__half2*)&O[(size_t)r0g * DIM + col] =
            __floats2half2_rn(o[dt][0] * i0, o[dt][1] * i0);
        *(__half2*)&O[(size_t)r1g * DIM + col] =
            __floats2half2_rn(o[dt][2] * i1, o[dt][3] * i1);
    }
}

// ---------------- launch ----------------
extern "C" void kernel_launch(void* const* d_in, const int* in_sizes, int n_in,
                              void* d_out, int out_size) {
    const float* x  = (const float*)d_in[0];
    const float* Wq = (const float*)d_in[1];
    const float* Wk = (const float*)d_in[2];
    const float* Wv = (const float*)d_in[3];
    const float* Wo = (const float*)d_in[4];
    float* out = (float*)d_out;

    int seq = in_sizes[0] / DIM;  // 4096

    __half *xh, *wqh, *wkh, *wvh, *woh, *q, *k, *v, *attn;
    cudaGetSymbolAddress((void**)&xh, g_xh);
    cudaGetSymbolAddress((void**)&wqh, g_wqh);
    cudaGetSymbolAddress((void**)&wkh, g_wkh);
    cudaGetSymbolAddress((void**)&wvh, g_wvh);
    cudaGetSymbolAddress((void**)&woh, g_woh);
    cudaGetSymbolAddress((void**)&q, g_q);
    cudaGetSymbolAddress((void**)&k, g_k);
    cudaGetSymbolAddress((void**)&v, g_v);
    cudaGetSymbolAddress((void**)&attn, g_attn);

    const int nX4 = seq * DIM / 4, nW4 = DIM * DIM / 4;
    conv_h<<<1184, 256>>>(x, xh, nX4);
    conv_h<<<1184, 256>>>(Wq, wqh, nW4);
    conv_h<<<1184, 256>>>(Wk, wkh, nW4);
    conv_h<<<1184, 256>>>(Wv, wvh, nW4);
    conv_h<<<1184, 256>>>(Wo, woh, nW4);

    const int smem_gemm = GSTAGES * 2 * 128 * HS * sizeof(__half);  // 81920
    cudaFuncSetAttribute(gemm_h<0>, cudaFuncAttributeMaxDynamicSharedMemorySize, smem_gemm);
    cudaFuncSetAttribute(gemm_h<1>, cudaFuncAttributeMaxDynamicSharedMemorySize, smem_gemm);
    cudaFuncSetAttribute(gemm_h<2>, cudaFuncAttributeMaxDynamicSharedMemorySize, smem_gemm);

    dim3 gg(DIM / 128, seq / 128);
    gemm_h<1><<<gg, 256, smem_gemm>>>(xh, wqh, q, seq);
    gemm_h<1><<<gg, 256, smem_gemm>>>(xh, wkh, k, seq);
    gemm_h<2><<<gg, 256, smem_gemm>>>(xh, wvh, v, seq);

    cudaFuncSetAttribute(attn_h, cudaFuncAttributeMaxDynamicSharedMemorySize, AT_SMEM);
    attn_h<<<dim3(seq / AQ, NHEADS), 256, AT_SMEM>>>(q, k, v, attn, seq);

    gemm_h<0><<<gg, 256, smem_gemm>>>(attn, woh, out, seq);
}